// round 17
// baseline (speedup 1.0000x reference)
#include <cuda_runtime.h>
#include <cuda_fp16.h>
#include <math.h>
#include <stdint.h>

#define B_   2
#define S_   2048
#define HID_ 2048
#define H_   16
#define KV_  8
#define D_   128
#define MROWS (B_ * S_)   // 4096

// ---------------------------------------------------------------------------
// Scratch (__device__ globals; allocation-free rule)
// ---------------------------------------------------------------------------
__device__ __half g_x16[(size_t)MROWS * HID_];
__device__ __half g_qw16[(size_t)H_ * D_ * HID_];
__device__ __half g_kw16[(size_t)KV_ * D_ * HID_];
__device__ __half g_vw16[(size_t)KV_ * D_ * HID_];
__device__ __half g_ow16[(size_t)HID_ * H_ * D_];
__device__ __half g_q16[(size_t)MROWS * H_ * D_];
__device__ __half g_k16[(size_t)MROWS * KV_ * D_];
__device__ __half g_v16[(size_t)MROWS * KV_ * D_];
__device__ __half g_at16[(size_t)MROWS * H_ * D_];

// ---------------------------------------------------------------------------
// Helpers
// ---------------------------------------------------------------------------
__device__ __forceinline__ uint32_t smem_u32(const void* p) {
    uint32_t a;
    asm("{ .reg .u64 t; cvta.to.shared.u64 t, %1; cvt.u32.u64 %0, t; }"
        : "=r"(a) : "l"(p));
    return a;
}

__device__ __forceinline__ void cpasync16(uint32_t dst, const void* src) {
    asm volatile("cp.async.cg.shared.global [%0], [%1], 16;" :: "r"(dst), "l"(src));
}

#define LDSM_X4(r0, r1, r2, r3, addr)                                         \
    asm volatile("ldmatrix.sync.aligned.m8n8.x4.shared.b16 {%0,%1,%2,%3}, [%4];" \
                 : "=r"(r0), "=r"(r1), "=r"(r2), "=r"(r3) : "r"(addr))

#define LDSM_X4_T(r0, r1, r2, r3, addr)                                       \
    asm volatile("ldmatrix.sync.aligned.m8n8.x4.trans.shared.b16 {%0,%1,%2,%3}, [%4];" \
                 : "=r"(r0), "=r"(r1), "=r"(r2), "=r"(r3) : "r"(addr))

__device__ __forceinline__ void ldsm_x4(uint32_t& r0, uint32_t& r1,
                                        uint32_t& r2, uint32_t& r3, uint32_t addr) {
    LDSM_X4(r0, r1, r2, r3, addr);
}

// fp16 mma, fp32 accum
__device__ __forceinline__ void mma_h(float* c, const uint32_t* a,
                                      uint32_t b0, uint32_t b1) {
    asm volatile("mma.sync.aligned.m16n8k16.row.col.f32.f16.f16.f32 "
                 "{%0,%1,%2,%3}, {%4,%5,%6,%7}, {%8,%9}, {%0,%1,%2,%3};"
                 : "+f"(c[0]), "+f"(c[1]), "+f"(c[2]), "+f"(c[3])
                 : "r"(a[0]), "r"(a[1]), "r"(a[2]), "r"(a[3]), "r"(b0), "r"(b1));
}

__device__ __forceinline__ uint32_t pkh(float a, float b) {
    __half2 h = __floats2half2_rn(a, b);
    return *(uint32_t*)&h;
}

// ---------------------------------------------------------------------------
// Fused convert kernel: all five arrays -> single fp16.
// ---------------------------------------------------------------------------
#define NX4  (MROWS * HID_ / 4)        // 2097152
#define NQW4 (H_ * D_ * HID_ / 4)      // 1048576
#define NKW4 (KV_ * D_ * HID_ / 4)     // 524288
#define NSPLIT_TOT (NX4 + 2 * NQW4 + 2 * NKW4)   // 5242880

__device__ __forceinline__ void cvt_single(float4 v, __half* o16, int i) {
    uint2 p = make_uint2(pkh(v.x, v.y), pkh(v.z, v.w));
    *(uint2*)(o16 + 4 * (size_t)i) = p;
}

__global__ __launch_bounds__(256) void split5(
    const float4* __restrict__ x,  const float4* __restrict__ qw,
    const float4* __restrict__ kw, const float4* __restrict__ vw,
    const float4* __restrict__ ow,
    __half* x16, __half* qw16, __half* kw16, __half* vw16, __half* ow16)
{
    auto proc = [&](int i) {
        if (i < NX4) { cvt_single(x[i], x16, i); return; }
        i -= NX4;
        if (i < NQW4) { cvt_single(qw[i], qw16, i); return; }
        i -= NQW4;
        if (i < NKW4) { cvt_single(kw[i], kw16, i); return; }
        i -= NKW4;
        if (i < NKW4) { cvt_single(vw[i], vw16, i); return; }
        i -= NKW4;
        cvt_single(ow[i], ow16, i);
    };
    int gid = blockIdx.x * 256 + threadIdx.x;
    proc(2 * gid);
    proc(2 * gid + 1);
}

// ---------------------------------------------------------------------------
// fp16 mma.sync GEMM mainloop (validated): acc += A B^T for a 128x128 tile.
// 256 threads / 8 warps (2x4), warp tile 64x32.
// ---------------------------------------------------------------------------
#define GK_      32
#define RSTR_B   80u
#define TILE_B   (128u * RSTR_B)
#define STAGE_B1 (2u * TILE_B)        // 20480
#define GEMM_SMEM (2 * 20480)
#define QKV_SMEM  (128 * 132 * 4 + 128 * 4 * 4)   // 69632 (>= GEMM_SMEM)

__device__ __forceinline__ void g_fill1(
    uint32_t dst, const __half* A16, const __half* B16,
    int m0, int n0, int K, int k0, int tid)
{
#pragma unroll
    for (int i = 0; i < 4; i++) {
        int idx = tid + i * 256;
        int t   = idx >> 9;          // 0:A 1:B
        int rem = idx & 511;
        int r   = rem >> 2;
        int seg = rem & 3;
        const __half* src = (t == 0) ? A16 + (size_t)(m0 + r) * K + k0 + seg * 8
                                     : B16 + (size_t)(n0 + r) * K + k0 + seg * 8;
        uint32_t d = dst + (uint32_t)t * TILE_B + (uint32_t)r * RSTR_B + (uint32_t)seg * 16u;
        cpasync16(d, src);
    }
}

__device__ __forceinline__ void gemm_mainloop(
    const __half* A16, const __half* B16, int K, int m0, int n0,
    uint32_t sb, int tid, int wid, int lane, int wm, int wn,
    float acc[4][4][4])
{
    const uint32_t aoff = (uint32_t)(wm + (lane & 15)) * RSTR_B + (uint32_t)((lane >> 4) * 16);
    const uint32_t boff = (uint32_t)(wn + ((lane >> 4) << 3) + (lane & 7)) * RSTR_B
                        + (uint32_t)(((lane >> 3) & 1) * 16);

    g_fill1(sb, A16, B16, m0, n0, K, 0, tid);
    asm volatile("cp.async.commit_group;");

    const int nit = K / GK_;
    for (int it = 0; it < nit; ++it) {
        const int cur = it & 1;
        if (it + 1 < nit) {
            g_fill1(sb + (uint32_t)(cur ^ 1) * STAGE_B1, A16, B16,
                    m0, n0, K, (it + 1) * GK_, tid);
            asm volatile("cp.async.commit_group;");
            asm volatile("cp.async.wait_group 1;");
        } else {
            asm volatile("cp.async.wait_group 0;");
        }
        __syncthreads();

        const uint32_t stg = sb + (uint32_t)cur * STAGE_B1;
        const uint32_t sA  = stg;
        const uint32_t sB  = stg + TILE_B;

#pragma unroll
        for (int kh = 0; kh < 2; kh++) {
            const uint32_t kb = (uint32_t)kh * 32u;
            uint32_t ah[4][4], bh[4][2];
#pragma unroll
            for (int mi = 0; mi < 4; mi++)
                ldsm_x4(ah[mi][0], ah[mi][1], ah[mi][2], ah[mi][3],
                        sA + aoff + (uint32_t)(mi * 16) * RSTR_B + kb);
#pragma unroll
            for (int nt = 0; nt < 2; nt++) {
                uint32_t r0, r1, r2, r3;
                ldsm_x4(r0, r1, r2, r3, sB + boff + (uint32_t)(nt * 16) * RSTR_B + kb);
                bh[nt * 2 + 0][0] = r0; bh[nt * 2 + 0][1] = r1;
                bh[nt * 2 + 1][0] = r2; bh[nt * 2 + 1][1] = r3;
            }
#pragma unroll
            for (int mi = 0; mi < 4; mi++)
#pragma unroll
                for (int ni = 0; ni < 4; ni++)
                    mma_h(acc[mi][ni], ah[mi], bh[ni][0], bh[ni][1]);
        }
        __syncthreads();
    }
}

// ---------------------------------------------------------------------------
// O-projection GEMM: fp32 output (final result).
// ---------------------------------------------------------------------------
__global__ __launch_bounds__(256, 2) void gemm_fp16(
    const __half* __restrict__ A16, const __half* __restrict__ B16,
    float* __restrict__ C, int N, int K)
{
    extern __shared__ __align__(128) char smem[];
    const uint32_t sb = smem_u32(smem);
    const int tid = threadIdx.x, wid = tid >> 5, lane = tid & 31;
    const int wm = (wid >> 2) << 6, wn = (wid & 3) << 5;
    const int m0 = blockIdx.y << 7, n0 = blockIdx.x << 7;

    float acc[4][4][4];
#pragma unroll
    for (int mi = 0; mi < 4; mi++)
#pragma unroll
        for (int ni = 0; ni < 4; ni++)
#pragma unroll
            for (int r = 0; r < 4; r++) acc[mi][ni][r] = 0.f;

    gemm_mainloop(A16, B16, K, m0, n0, sb, tid, wid, lane, wm, wn, acc);

#pragma unroll
    for (int mi = 0; mi < 4; mi++) {
        const int row = m0 + wm + mi * 16 + (lane >> 2);
#pragma unroll
        for (int ni = 0; ni < 4; ni++) {
            const int col = n0 + wn + ni * 8 + (lane & 3) * 2;
            *(float2*)&C[(size_t)row * N + col] =
                make_float2(acc[mi][ni][0], acc[mi][ni][1]);
            *(float2*)&C[(size_t)(row + 8) * N + col] =
                make_float2(acc[mi][ni][2], acc[mi][ni][3]);
        }
    }
}

// ---------------------------------------------------------------------------
// Fused Q/K/V projection + RMSNorm + RoPE + fp16 convert.
// Each CTA computes 128 rows x one head (D=128); RMSNorm axis == tile cols.
// blocks x: [0,16) q-heads | [16,24) k-heads | [24,32) v-heads
// ---------------------------------------------------------------------------
__global__ __launch_bounds__(256, 2) void gemm_qkv(
    const __half* __restrict__ x16,
    const __half* __restrict__ qw16, const __half* __restrict__ kw16,
    const __half* __restrict__ vw16,
    const float* __restrict__ pe,
    const float* __restrict__ qnw, const float* __restrict__ knw,
    __half* __restrict__ q16, __half* __restrict__ k16,
    __half* __restrict__ v16, int K)
{
    extern __shared__ __align__(128) char smem[];
    const uint32_t sb = smem_u32(smem);
    const int tid = threadIdx.x, wid = tid >> 5, lane = tid & 31;
    const int wm = (wid >> 2) << 6, wn = (wid & 3) << 5;
    const int m0 = blockIdx.y << 7;

    const int bxx = blockIdx.x;
    const __half* B16; const float* nw = nullptr; __half* O;
    int nheads, head, mode;
    if (bxx < 16)      { B16 = qw16; nw = qnw; O = q16; nheads = H_;  head = bxx;      mode = 0; }
    else if (bxx < 24) { B16 = kw16; nw = knw; O = k16; nheads = KV_; head = bxx - 16; mode = 1; }
    else               { B16 = vw16;           O = v16; nheads = KV_; head = bxx - 24; mode = 2; }
    const int n0 = head << 7;

    float acc[4][4][4];
#pragma unroll
    for (int mi = 0; mi < 4; mi++)
#pragma unroll
        for (int ni = 0; ni < 4; ni++)
#pragma unroll
            for (int r = 0; r < 4; r++) acc[mi][ni][r] = 0.f;

    gemm_mainloop(x16, B16, K, m0, n0, sb, tid, wid, lane, wm, wn, acc);

    if (mode == 2) {
        // V: straight fp16 convert + store
#pragma unroll
        for (int mi = 0; mi < 4; mi++) {
            const int r0 = wm + mi * 16 + (lane >> 2);
            const size_t b0 = ((size_t)(m0 + r0) * nheads + head) * 128;
            const size_t b1 = ((size_t)(m0 + r0 + 8) * nheads + head) * 128;
#pragma unroll
            for (int ni = 0; ni < 4; ni++) {
                const int col = wn + ni * 8 + (lane & 3) * 2;
                *(uint32_t*)&O[b0 + col] = pkh(acc[mi][ni][0], acc[mi][ni][1]);
                *(uint32_t*)&O[b1 + col] = pkh(acc[mi][ni][2], acc[mi][ni][3]);
            }
        }
        return;
    }

    // ---- Q/K: RMSNorm over tile cols + RoPE, all fp32, then fp16 store ----
    float* xs   = (float*)smem;          // [128][132]
    float* rsum = xs + 128 * 132;        // [128][4]

    // 1) per-row sum of squares: thread-local, quad shfl, cross-warp via smem
#pragma unroll
    for (int mi = 0; mi < 4; mi++) {
        float s0 = 0.f, s1 = 0.f;
#pragma unroll
        for (int ni = 0; ni < 4; ni++) {
            s0 += acc[mi][ni][0] * acc[mi][ni][0] + acc[mi][ni][1] * acc[mi][ni][1];
            s1 += acc[mi][ni][2] * acc[mi][ni][2] + acc[mi][ni][3] * acc[mi][ni][3];
        }
        s0 += __shfl_xor_sync(0xffffffffu, s0, 1);
        s0 += __shfl_xor_sync(0xffffffffu, s0, 2);
        s1 += __shfl_xor_sync(0xffffffffu, s1, 1);
        s1 += __shfl_xor_sync(0xffffffffu, s1, 2);
        if ((lane & 3) == 0) {
            const int r = wm + mi * 16 + (lane >> 2);
            rsum[r * 4 + (wid & 3)] = s0;
            rsum[(r + 8) * 4 + (wid & 3)] = s1;
        }
    }
    __syncthreads();

    // 2) normalize * weight, stage xn in smem for the RoPE partner exchange
#pragma unroll
    for (int mi = 0; mi < 4; mi++) {
        const int r0 = wm + mi * 16 + (lane >> 2);
        const float t0 = rsum[r0 * 4] + rsum[r0 * 4 + 1] + rsum[r0 * 4 + 2] + rsum[r0 * 4 + 3];
        const float t1 = rsum[(r0 + 8) * 4] + rsum[(r0 + 8) * 4 + 1]
                       + rsum[(r0 + 8) * 4 + 2] + rsum[(r0 + 8) * 4 + 3];
        const float rn0 = rsqrtf(t0 * (1.f / 128.f) + 1e-6f);
        const float rn1 = rsqrtf(t1 * (1.f / 128.f) + 1e-6f);
#pragma unroll
        for (int ni = 0; ni < 4; ni++) {
            const int col = wn + ni * 8 + (lane & 3) * 2;
            const float w0 = nw[col], w1 = nw[col + 1];
            acc[mi][ni][0] *= rn0 * w0; acc[mi][ni][1] *= rn0 * w1;
            acc[mi][ni][2] *= rn1 * w0; acc[mi][ni][3] *= rn1 * w1;
            xs[r0 * 132 + col]           = acc[mi][ni][0];
            xs[r0 * 132 + col + 1]       = acc[mi][ni][1];
            xs[(r0 + 8) * 132 + col]     = acc[mi][ni][2];
            xs[(r0 + 8) * 132 + col + 1] = acc[mi][ni][3];
        }
    }
    __syncthreads();

    // 3) RoPE: partner at col^64 (warp-uniform half select), then fp16 store
    const bool low = (wid & 3) < 2;   // wn in {0,32} -> col < 64
#pragma unroll
    for (int mi = 0; mi < 4; mi++) {
        const int r0 = wm + mi * 16 + (lane >> 2);
        const float* pe0 = pe + (size_t)(m0 + r0) * 128;
        const float* pe1 = pe + (size_t)(m0 + r0 + 8) * 128;
        const size_t b0 = ((size_t)(m0 + r0) * nheads + head) * 128;
        const size_t b1 = ((size_t)(m0 + r0 + 8) * nheads + head) * 128;
#pragma unroll
        for (int ni = 0; ni < 4; ni++) {
            const int col = wn + ni * 8 + (lane & 3) * 2;
            const int dc  = col & 63;
            const int pc  = col ^ 64;
            const float p00 = xs[r0 * 132 + pc];
            const float p01 = xs[r0 * 132 + pc + 1];
            const float p10 = xs[(r0 + 8) * 132 + pc];
            const float p11 = xs[(r0 + 8) * 132 + pc + 1];
            const float2 c0 = *(const float2*)(pe0 + dc);
            const float2 s0 = *(const float2*)(pe0 + 64 + dc);
            const float2 c1 = *(const float2*)(pe1 + dc);
            const float2 s1 = *(const float2*)(pe1 + 64 + dc);
            float o00, o01, o10, o11;
            if (low) {
                o00 = acc[mi][ni][0] * c0.x - p00 * s0.x;
                o01 = acc[mi][ni][1] * c0.y - p01 * s0.y;
                o10 = acc[mi][ni][2] * c1.x - p10 * s1.x;
                o11 = acc[mi][ni][3] * c1.y - p11 * s1.y;
            } else {
                o00 = p00 * s0.x + acc[mi][ni][0] * c0.x;
                o01 = p01 * s0.y + acc[mi][ni][1] * c0.y;
                o10 = p10 * s1.x + acc[mi][ni][2] * c1.x;
                o11 = p11 * s1.y + acc[mi][ni][3] * c1.y;
            }
            *(uint32_t*)&O[b0 + col] = pkh(o00, o01);
            *(uint32_t*)&O[b1 + col] = pkh(o10, o11);
        }
    }
}

// ---------------------------------------------------------------------------
// Flash attention, all-single fp16, causal GQA. (validated R16, unchanged)
// BR=64 (4 warps x 16 rows), BC=64, 3-stage KV ring, 2 CTAs/SM.
// ---------------------------------------------------------------------------
#define F3STR   272u
#define F3_K    0u
#define F3_V    17408u
#define F3_STG  34816u
#define FLASH4_SMEM (3 * 34816)   // 104448

__global__ __launch_bounds__(128, 2) void flash_mma(
    const __half* __restrict__ Q16, const __half* __restrict__ K16,
    const __half* __restrict__ V16, __half* __restrict__ Oa)
{
    extern __shared__ __align__(16) char smem[];
    const uint32_t sb = smem_u32(smem);
    const int tid = threadIdx.x, lane = tid & 31, w = tid >> 5;
    const int bx = gridDim.x - 1 - blockIdx.x;   // heavy diagonals first
    const int h = blockIdx.y, b = blockIdx.z, kvh = h >> 1;
    const int g = lane >> 2, tg = lane & 3;
    const int ntiles = bx + 1;

    {
        const size_t qbase = (((size_t)b * S_ + (size_t)bx * 64) * H_ + h) * D_;
        const uint32_t qdst = sb + 2u * F3_STG;
#pragma unroll
        for (int i = 0; i < 8; i++) {
            int idx = tid + i * 128;
            int r = idx >> 4, seg = idx & 15;
            size_t src = qbase + (size_t)r * (H_ * D_) + seg * 8;
            cpasync16(qdst + (uint32_t)r * F3STR + (uint32_t)seg * 16u, Q16 + src);
        }
    }
    asm volatile("cp.async.commit_group;");

    auto fillKV = [&](int stage, int kt) {
        const size_t kbase = (((size_t)b * S_ + (size_t)kt * 64) * KV_ + kvh) * D_;
        const uint32_t sdst = sb + (uint32_t)stage * F3_STG;
#pragma unroll
        for (int i = 0; i < 8; i++) {
            int idx = tid + i * 128;
            int r = idx >> 4, seg = idx & 15;
            size_t src = kbase + (size_t)r * (KV_ * D_) + seg * 8;
            uint32_t dst = sdst + (uint32_t)r * F3STR + (uint32_t)seg * 16u;
            cpasync16(dst + F3_K, K16 + src);
            cpasync16(dst + F3_V, V16 + src);
        }
        asm volatile("cp.async.commit_group;");
    };

    fillKV(0, 0);
    fillKV(1, 1);

    asm volatile("cp.async.wait_group 2;");
    __syncthreads();

    uint32_t qf[8][4];
    {
        const uint32_t aQ = sb + 2u * F3_STG
                          + (uint32_t)(w * 16 + (lane & 15)) * F3STR
                          + (uint32_t)((lane >> 4) * 16);
#pragma unroll
        for (int kb = 0; kb < 8; kb++)
            ldsm_x4(qf[kb][0], qf[kb][1], qf[kb][2], qf[kb][3], aQ + kb * 32);
    }

    float o[16][4];
#pragma unroll
    for (int i = 0; i < 16; i++)
#pragma unroll
        for (int j = 0; j < 4; j++) o[i][j] = 0.f;
    float m0 = -1e30f, m1 = -1e30f, l0 = 0.f, l1 = 0.f;

    const int qr0 = bx * 64 + w * 16 + g;
    const float sca2 = 0.12751744f;   // log2(e)/sqrt(128)

    int cur = 0;
    for (int kt = 0; kt < ntiles; kt++) {
        if (kt + 1 < ntiles) {
            asm volatile("cp.async.wait_group 1;");
        } else {
            asm volatile("cp.async.wait_group 0;");
        }
        __syncthreads();
        if (kt + 2 < ntiles) {
            int fs = cur + 2; if (fs >= 3) fs -= 3;
            fillKV(fs, kt + 2);
        }

        if (kt * 64 <= bx * 64 + w * 16 + 15) {
            const uint32_t stg = sb + (uint32_t)cur * F3_STG;
            const uint32_t bK  = stg + F3_K
                               + (uint32_t)((((lane >> 4) << 3) + (lane & 7)) * F3STR)
                               + (uint32_t)(((lane >> 3) & 1) * 16);

            float sc[8][4];
#pragma unroll
            for (int i = 0; i < 8; i++)
#pragma unroll
                for (int j = 0; j < 4; j++) sc[i][j] = 0.f;

#pragma unroll
            for (int kb = 0; kb < 8; kb++) {
#pragma unroll
                for (int nt = 0; nt < 4; nt++) {
                    uint32_t k0, k1, k2, k3;
                    ldsm_x4(k0, k1, k2, k3,
                            bK + (uint32_t)(nt * 16) * F3STR + kb * 32);
                    mma_h(sc[2 * nt],     qf[kb], k0, k1);
                    mma_h(sc[2 * nt + 1], qf[kb], k2, k3);
                }
            }

            const bool maskt = (kt * 64 + 63 > bx * 64 + w * 16);
            const int row0 = qr0, row1 = qr0 + 8, cb = kt * 64;
#pragma unroll
            for (int nt = 0; nt < 8; nt++) {
                int c0 = cb + nt * 8 + tg * 2;
                float v0 = sc[nt][0] * sca2, v1 = sc[nt][1] * sca2;
                float v2 = sc[nt][2] * sca2, v3 = sc[nt][3] * sca2;
                if (maskt) {
                    if (c0     > row0) v0 = -1e30f;
                    if (c0 + 1 > row0) v1 = -1e30f;
                    if (c0     > row1) v2 = -1e30f;
                    if (c0 + 1 > row1) v3 = -1e30f;
                }
                sc[nt][0] = v0; sc[nt][1] = v1; sc[nt][2] = v2; sc[nt][3] = v3;
            }

            float mx0 = -1e30f, mx1 = -1e30f;
#pragma unroll
            for (int nt = 0; nt < 8; nt++) {
                mx0 = fmaxf(mx0, fmaxf(sc[nt][0], sc[nt][1]));
                mx1 = fmaxf(mx1, fmaxf(sc[nt][2], sc[nt][3]));
            }
            mx0 = fmaxf(mx0, __shfl_xor_sync(0xffffffffu, mx0, 1));
            mx0 = fmaxf(mx0, __shfl_xor_sync(0xffffffffu, mx0, 2));
            mx1 = fmaxf(mx1, __shfl_xor_sync(0xffffffffu, mx1, 1));
            mx1 = fmaxf(mx1, __shfl_xor_sync(0xffffffffu, mx1, 2));
            const float mn0 = fmaxf(m0, mx0), mn1 = fmaxf(m1, mx1);
            const float al0 = exp2f(m0 - mn0), al1 = exp2f(m1 - mn1);
            m0 = mn0; m1 = mn1;
#pragma unroll
            for (int nt = 0; nt < 16; nt++) {
                o[nt][0] *= al0; o[nt][1] *= al0;
                o[nt][2] *= al1; o[nt][3] *= al1;
            }

            float s0 = 0.f, s1 = 0.f;
#pragma unroll
            for (int j = 0; j < 4; j++) {
                float p00 = exp2f(sc[2 * j][0] - mn0);
                float p01 = exp2f(sc[2 * j][1] - mn0);
                float p02 = exp2f(sc[2 * j][2] - mn1);
                float p03 = exp2f(sc[2 * j][3] - mn1);
                float p10 = exp2f(sc[2 * j + 1][0] - mn0);
                float p11 = exp2f(sc[2 * j + 1][1] - mn0);
                float p12 = exp2f(sc[2 * j + 1][2] - mn1);
                float p13 = exp2f(sc[2 * j + 1][3] - mn1);
                s0 += (p00 + p01) + (p10 + p11);
                s1 += (p02 + p03) + (p12 + p13);

                uint32_t ph[4];
                ph[0] = pkh(p00, p01);
                ph[1] = pkh(p02, p03);
                ph[2] = pkh(p10, p11);
                ph[3] = pkh(p12, p13);

                const uint32_t vrow = stg + F3_V
                    + (uint32_t)((j * 16 + ((lane >> 3) & 1) * 8 + (lane & 7)) * F3STR)
                    + (uint32_t)((lane >> 4) * 16);
#pragma unroll
                for (int ntp = 0; ntp < 8; ntp++) {
                    uint32_t vh0, vh1, vh2, vh3;
                    LDSM_X4_T(vh0, vh1, vh2, vh3, vrow + ntp * 32);
                    mma_h(o[2 * ntp],     ph, vh0, vh1);
                    mma_h(o[2 * ntp + 1], ph, vh2, vh3);
                }
            }
            s0 += __shfl_xor_sync(0xffffffffu, s0, 1);
            s0 += __shfl_xor_sync(0xffffffffu, s0, 2);
            s1 += __shfl_xor_sync(0xffffffffu, s1, 1);
            s1 += __shfl_xor_sync(0xffffffffu, s1, 2);
            l0 = l0 * al0 + s0;
            l1 = l1 * al1 + s1;
        }
        if (++cur == 3) cur = 0;
    }

    const float i0 = 1.f / l0, i1 = 1.f / l1;
    const size_t o0 = (((size_t)b * S_ + (size_t)qr0) * H_ + h) * D_;
    const size_t o1 = o0 + (size_t)8 * (H_ * D_);
#pragma unroll
    for (int nt = 0; nt < 16; nt++) {
        const int col = nt * 8 + tg * 2;
        *(uint32_t*)&Oa[o0 + col] = pkh(o[nt][0] * i0, o[nt][1] * i0);
        *(uint32_t*)&Oa[o1 + col] = pkh(o[nt][2] * i1, o[nt][3] * i1);
    }
}

// ---------------------------------------------------------------------------
extern "C" void kernel_launch(void* const* d_in, const int* in_sizes, int n_in,
                              void* d_out, int out_size)
{
    const float* x   = (const float*)d_in[0];
    const float* pe  = (const float*)d_in[1];
    const float* q_w = (const float*)d_in[2];
    const float* k_w = (const float*)d_in[3];
    const float* v_w = (const float*)d_in[4];
    const float* o_w = (const float*)d_in[5];
    const float* qnw = (const float*)d_in[6];
    const float* knw = (const float*)d_in[7];
    float* out = (float*)d_out;

    __half *x16, *qw16, *kw16, *vw16, *ow16;
    __half *q16, *k16, *v16, *at16;
    cudaGetSymbolAddress((void**)&x16,  g_x16);
    cudaGetSymbolAddress((void**)&qw16, g_qw16);
    cudaGetSymbolAddress((void**)&kw16, g_kw16);
    cudaGetSymbolAddress((void**)&vw16, g_vw16);
    cudaGetSymbolAddress((void**)&ow16, g_ow16);
    cudaGetSymbolAddress((void**)&q16,  g_q16);
    cudaGetSymbolAddress((void**)&k16,  g_k16);
    cudaGetSymbolAddress((void**)&v16,  g_v16);
    cudaGetSymbolAddress((void**)&at16, g_at16);

    cudaFuncSetAttribute(gemm_fp16, cudaFuncAttributeMaxDynamicSharedMemorySize,
                         GEMM_SMEM);
    cudaFuncSetAttribute(gemm_qkv, cudaFuncAttributeMaxDynamicSharedMemorySize,
                         QKV_SMEM);
    cudaFuncSetAttribute(flash_mma, cudaFuncAttributeMaxDynamicSharedMemorySize,
                         FLASH4_SMEM);

    // 1) fused converts: all inputs -> single fp16
    split5<<<NSPLIT_TOT / 512, 256>>>(
        (const float4*)x, (const float4*)q_w, (const float4*)k_w,
        (const float4*)v_w, (const float4*)o_w,
        x16, qw16, kw16, vw16, ow16);

    // 2) fused Q/K/V projections + RMSNorm + RoPE + fp16 convert (one launch)
    gemm_qkv<<<dim3(32, 32), 256, QKV_SMEM>>>(x16, qw16, kw16, vw16,
                                              pe, qnw, knw, q16, k16, v16, HID_);

    // 3) causal GQA flash attention (all single fp16, BC=64; 2 CTAs/SM)
    flash_mma<<<dim3(S_ / 64, H_, B_), 128, FLASH4_SMEM>>>(
        q16, k16, v16, at16);

    // 4) output projection (fp16 mma.sync, 2 CTAs/SM)
    gemm_fp16<<<dim3(16, 32), 256, GEMM_SMEM>>>(at16, ow16, out, HID_, HID_);
}